// round 5
// baseline (speedup 1.0000x reference)
#include <cuda_runtime.h>

#define MAXN   100000
#define MAXE   3200000
#define IN_DIM 128
#define HID    64
#define G_NUM  256
#define SCAN_B 1024

// ---------------- device scratch (no allocation allowed) ----------------
__device__ __align__(16) float g_h   [MAXN * (size_t)HID];  // GEMM output (xl)
__device__ __align__(16) float g_acc [MAXN * (size_t)HID];  // gathered layer output
__device__ __align__(16) float2 g_edge[MAXE];               // {row bits, norm} per CSR slot
__device__ float g_deg [MAXN];
__device__ float g_dis [MAXN];
__device__ int   g_cntn[MAXN];           // in-degree counts
__device__ int   g_off [MAXN];           // CSR offsets (exclusive scan)
__device__ int   g_cur [MAXN];           // placement cursors
__device__ int   g_bsum[(MAXN + SCAN_B - 1) / SCAN_B];
__device__ int   g_boff[(MAXN + SCAN_B - 1) / SCAN_B];
__device__ int   g_gs  [G_NUM + 1];      // per-graph start offsets (batch sorted)
__device__ int   g_gcnt[G_NUM];
__device__ __align__(16) float g_sums[G_NUM * HID];

// ---------------- kernels ----------------

__global__ void k_reset(int n) {
    int i = blockIdx.x * blockDim.x + threadIdx.x;
    if (i < n) { g_deg[i] = 1.0f; g_cntn[i] = 0; }   // self-loop weight 1
}

// in-degree weight sum + edge count histogram  (indices are INT32!)
__global__ void k_deg(const int* __restrict__ col,
                      const float* __restrict__ ew, int E) {
    int e = blockIdx.x * blockDim.x + threadIdx.x;
    if (e < E) {
        int c = col[e];
        atomicAdd(&g_deg[c], ew[e]);
        atomicAdd(&g_cntn[c], 1);
    }
}

__global__ void k_dis(int n) {
    int i = blockIdx.x * blockDim.x + threadIdx.x;
    if (i < n) g_dis[i] = rsqrtf(g_deg[i]);          // deg >= 1 always
}

// ---- 3-kernel exclusive scan over g_cntn -> g_off ----
__global__ void k_scan1(int n) {
    __shared__ int s[2][SCAN_B];
    const int t = threadIdx.x;
    const int i = blockIdx.x * SCAN_B + t;
    int v = (i < n) ? g_cntn[i] : 0;
    s[0][t] = v;
    __syncthreads();
    int src = 0;
    #pragma unroll
    for (int d = 1; d < SCAN_B; d <<= 1) {
        int x = s[src][t];
        if (t >= d) x += s[src][t - d];
        s[1 - src][t] = x;
        src = 1 - src;
        __syncthreads();
    }
    int incl = s[src][t];
    if (i < n) g_off[i] = incl - v;                  // exclusive (within block)
    if (t == SCAN_B - 1) g_bsum[blockIdx.x] = incl;
}

__global__ void k_scan2(int nb) {
    if (threadIdx.x == 0) {
        int run = 0;
        for (int b = 0; b < nb; b++) { g_boff[b] = run; run += g_bsum[b]; }
    }
}

__global__ void k_scan3(int n) {
    int i = blockIdx.x * blockDim.x + threadIdx.x;
    if (i < n) {
        int o = g_off[i] + g_boff[i >> 10];
        g_off[i] = o;
        g_cur[i] = o;
    }
}

// scatter edges into CSR slots; norm computed inline
__global__ void k_place(const int* __restrict__ row,
                        const int* __restrict__ col,
                        const float* __restrict__ ew, int E) {
    int e = blockIdx.x * blockDim.x + threadIdx.x;
    if (e >= E) return;
    int r = row[e];
    int c = col[e];
    float nm = g_dis[r] * ew[e] * g_dis[c];
    int pos = atomicAdd(&g_cur[c], 1);
    g_edge[pos] = make_float2(__int_as_float(r), nm);
}

// GEMM: g_h[n][HID] = X[n][K] @ W[K][HID]; SRC_ACC reads relu(g_acc) instead of X
template<int K, bool SRC_ACC>
__global__ void k_gemm(const float* __restrict__ X,
                       const float* __restrict__ W, int n) {
    __shared__ float sw[K * HID];
    __shared__ float sx[16 * K];
    const int t = threadIdx.x;
    const int row0 = blockIdx.x * 16;

    #pragma unroll
    for (int i = t; i < K * HID / 4; i += 256)
        ((float4*)sw)[i] = ((const float4*)W)[i];

    const float4* xsrc = SRC_ACC
        ? (const float4*)(g_acc + (size_t)row0 * K)
        : (const float4*)(X     + (size_t)row0 * K);
    #pragma unroll
    for (int i = t; i < 16 * K / 4; i += 256) {
        float4 v = xsrc[i];
        if (SRC_ACC) {
            v.x = fmaxf(v.x, 0.0f); v.y = fmaxf(v.y, 0.0f);
            v.z = fmaxf(v.z, 0.0f); v.w = fmaxf(v.w, 0.0f);
        }
        ((float4*)sx)[i] = v;
    }
    __syncthreads();

    const int r  = t >> 4;
    const int hq = t & 15;
    float4 acc = make_float4(0.f, 0.f, 0.f, 0.f);
    const float* xr = sx + r * K;
    #pragma unroll 8
    for (int k = 0; k < K; k++) {
        const float xv = xr[k];
        const float4 w = ((const float4*)(sw + k * HID))[hq];
        acc.x += xv * w.x; acc.y += xv * w.y;
        acc.z += xv * w.z; acc.w += xv * w.w;
    }
    const int grow = row0 + r;
    if (grow < n)
        ((float4*)(g_h + (size_t)grow * HID))[hq] = acc;
}

// per-node CSR gather: 16 lanes/node, each lane owns one float4 column chunk.
// acc = bias + self-loop (dis^2 * own row) + sum_e norm_e * h[row_e]
__global__ void k_gather(const float* __restrict__ b, int n) {
    int tid = blockIdx.x * blockDim.x + threadIdx.x;
    int node = tid >> 4;
    if (node >= n) return;
    const int q = tid & 15;

    float4 acc = ((const float4*)b)[q];
    const float d = g_dis[node];
    const float dd = d * d;
    float4 h0 = ((const float4*)(g_h + (size_t)node * HID))[q];
    acc.x += h0.x * dd; acc.y += h0.y * dd;
    acc.z += h0.z * dd; acc.w += h0.w * dd;

    int e = g_off[node];
    const int e_end = e + g_cntn[node];

    for (; e + 1 < e_end; e += 2) {
        float2 r0 = g_edge[e];
        float2 r1 = g_edge[e + 1];
        float4 v0 = ((const float4*)(g_h + (size_t)__float_as_int(r0.x) * HID))[q];
        float4 v1 = ((const float4*)(g_h + (size_t)__float_as_int(r1.x) * HID))[q];
        acc.x += r0.y * v0.x + r1.y * v1.x;
        acc.y += r0.y * v0.y + r1.y * v1.y;
        acc.z += r0.y * v0.z + r1.y * v1.z;
        acc.w += r0.y * v0.w + r1.y * v1.w;
    }
    if (e < e_end) {
        float2 r0 = g_edge[e];
        float4 v0 = ((const float4*)(g_h + (size_t)__float_as_int(r0.x) * HID))[q];
        acc.x += r0.y * v0.x; acc.y += r0.y * v0.y;
        acc.z += r0.y * v0.z; acc.w += r0.y * v0.w;
    }
    ((float4*)(g_acc + (size_t)node * HID))[q] = acc;
}

// per-graph start offsets from the sorted batch vector (INT32)
__global__ void k_gs(const int* __restrict__ batch, int n) {
    int i = blockIdx.x * blockDim.x + threadIdx.x;
    if (i >= n) return;
    int b = batch[i];
    int p = (i == 0) ? -1 : batch[i - 1];
    for (int g = p + 1; g <= b; ++g) g_gs[g] = i;
    if (i == n - 1)
        for (int g = b + 1; g <= G_NUM; ++g) g_gs[g] = n;
}

// one CTA per graph: sum relu(g_acc) over the graph's contiguous node range
__global__ void k_pool(int n) {
    const int g = blockIdx.x;
    const int t = threadIdx.x;
    const int q = t & 15;
    const int sub = t >> 4;          // 16 sub-rows
    const int s = g_gs[g], e = g_gs[g + 1];

    float4 acc = make_float4(0.f, 0.f, 0.f, 0.f);
    for (int i = s + sub; i < e; i += 16) {
        float4 v = ((const float4*)(g_acc + (size_t)i * HID))[q];
        acc.x += fmaxf(v.x, 0.f); acc.y += fmaxf(v.y, 0.f);
        acc.z += fmaxf(v.z, 0.f); acc.w += fmaxf(v.w, 0.f);
    }
    __shared__ float4 sm[256];
    sm[t] = acc;
    __syncthreads();
    if (sub == 0) {
        float4 a = acc;
        #pragma unroll
        for (int k = 1; k < 16; k++) {
            float4 bb = sm[k * 16 + q];
            a.x += bb.x; a.y += bb.y; a.z += bb.z; a.w += bb.w;
        }
        ((float4*)(g_sums + g * HID))[q] = a;
        if (q == 0) g_gcnt[g] = e - s;
    }
}

__global__ void k_final(const float* __restrict__ Wc,
                        const float* __restrict__ bc,
                        float* __restrict__ out) {
    int g = blockIdx.x * blockDim.x + threadIdx.x;
    if (g >= G_NUM) return;
    const float c = fmaxf((float)g_gcnt[g], 1.0f);
    float acc = 0.0f;
    #pragma unroll
    for (int h = 0; h < HID; h++)
        acc += g_sums[g * HID + h] * Wc[h];
    out[g] = acc / c + bc[0];
}

// ---------------- launcher ----------------
extern "C" void kernel_launch(void* const* d_in, const int* in_sizes, int n_in,
                              void* d_out, int out_size) {
    const float* x     = (const float*)d_in[0];
    const int*   ei    = (const int*)  d_in[1];   // JAX x64 disabled -> int32!
    const float* ew    = (const float*)d_in[2];
    const int*   batch = (const int*)  d_in[3];   // int32!
    const float* W1    = (const float*)d_in[4];
    const float* b1    = (const float*)d_in[5];
    const float* W2    = (const float*)d_in[6];
    const float* b2    = (const float*)d_in[7];
    const float* Wc    = (const float*)d_in[8];
    const float* bc    = (const float*)d_in[9];
    float* out = (float*)d_out;

    const int n = in_sizes[0] / IN_DIM;   // 100000
    const int E = in_sizes[2];            // 3200000
    const int* row = ei;                  // ei[0, :]
    const int* col = ei + E;              // ei[1, :]
    const int T = 256;
    const int nb = (n + SCAN_B - 1) / SCAN_B;

    // normalization + CSR build
    k_reset<<<(n + T - 1) / T, T>>>(n);
    k_deg  <<<(E + T - 1) / T, T>>>(col, ew, E);
    k_dis  <<<(n + T - 1) / T, T>>>(n);
    k_scan1<<<nb, SCAN_B>>>(n);
    k_scan2<<<1, 32>>>(nb);
    k_scan3<<<(n + T - 1) / T, T>>>(n);
    k_place<<<(E + T - 1) / T, T>>>(row, col, ew, E);
    k_gs   <<<(n + T - 1) / T, T>>>(batch, n);

    // layer 1
    k_gemm<IN_DIM, false><<<(n + 15) / 16, T>>>(x, W1, n);
    k_gather<<<(n * 16 + T - 1) / T, T>>>(b1, n);

    // layer 2
    k_gemm<HID, true><<<(n + 15) / 16, T>>>(nullptr, W2, n);
    k_gather<<<(n * 16 + T - 1) / T, T>>>(b2, n);

    // pool + head
    k_pool <<<G_NUM, 256>>>(n);
    k_final<<<1, T>>>(Wc, bc, out);
}

// round 7
// speedup vs baseline: 1.2739x; 1.2739x over previous
#include <cuda_runtime.h>

#define MAXN   100000
#define MAXE   3200000
#define IN_DIM 128
#define HID    64
#define G_NUM  256
#define SCAN_B 1024

typedef unsigned long long u64;

// packed fp32x2 helpers (sm_100+): doubles fp32 FMA throughput per issue slot
__device__ __forceinline__ u64 pack2(float lo, float hi) {
    u64 r; asm("mov.b64 %0, {%1, %2};" : "=l"(r) : "f"(lo), "f"(hi)); return r;
}
__device__ __forceinline__ u64 ffma2(u64 a, u64 b, u64 c) {
    u64 d; asm("fma.rn.f32x2 %0, %1, %2, %3;" : "=l"(d) : "l"(a), "l"(b), "l"(c)); return d;
}
__device__ __forceinline__ float2 unpack2(u64 v) {
    float2 f; asm("mov.b64 {%0, %1}, %2;" : "=f"(f.x), "=f"(f.y) : "l"(v)); return f;
}

// ---------------- device scratch (no allocation allowed) ----------------
__device__ __align__(16) float g_h   [MAXN * (size_t)HID];  // GEMM output (xl)
__device__ __align__(16) float g_acc [MAXN * (size_t)HID];  // gathered layer output
__device__ __align__(16) float2 g_edge[MAXE];               // {row bits, dis[row]*ew}
__device__ float g_deg [MAXN];
__device__ float g_dis [MAXN];
__device__ int   g_cntn[MAXN];           // in-degree counts
__device__ int   g_off [MAXN + 1];       // CSR offsets (exclusive scan) + sentinel E
__device__ int   g_cur [MAXN];           // placement cursors
__device__ int   g_bsum[(MAXN + SCAN_B - 1) / SCAN_B];
__device__ int   g_boff[(MAXN + SCAN_B - 1) / SCAN_B];
__device__ int   g_gs  [G_NUM + 1];      // per-graph start offsets (batch sorted)
__device__ int   g_gcnt[G_NUM];
__device__ __align__(16) float g_sums[G_NUM * HID];

// ---------------- kernels ----------------

__global__ void k_reset(int n) {
    int i = blockIdx.x * blockDim.x + threadIdx.x;
    if (i < n) { g_deg[i] = 1.0f; g_cntn[i] = 0; }   // self-loop weight 1
}

// in-degree weight sum + edge count histogram (indices are int32)
__global__ void k_deg(const int* __restrict__ col,
                      const float* __restrict__ ew, int E) {
    int e = blockIdx.x * blockDim.x + threadIdx.x;
    if (e < E) {
        int c = col[e];
        atomicAdd(&g_deg[c], ew[e]);
        atomicAdd(&g_cntn[c], 1);
    }
}

// block-local exclusive scan over g_cntn (+ fused dis = rsqrt(deg))
__global__ void k_scan1(int n) {
    __shared__ int s[2][SCAN_B];
    const int t = threadIdx.x;
    const int i = blockIdx.x * SCAN_B + t;
    if (i < n) g_dis[i] = rsqrtf(g_deg[i]);          // deg >= 1 always
    int v = (i < n) ? g_cntn[i] : 0;
    s[0][t] = v;
    __syncthreads();
    int src = 0;
    #pragma unroll
    for (int d = 1; d < SCAN_B; d <<= 1) {
        int x = s[src][t];
        if (t >= d) x += s[src][t - d];
        s[1 - src][t] = x;
        src = 1 - src;
        __syncthreads();
    }
    int incl = s[src][t];
    if (i < n) g_off[i] = incl - v;                  // exclusive within block
    if (t == SCAN_B - 1) g_bsum[blockIdx.x] = incl;
}

// parallel scan of block sums (nb <= 128)
__global__ void k_scan2(int nb) {
    __shared__ int s[128];
    const int t = threadIdx.x;
    int v = (t < nb) ? g_bsum[t] : 0;
    s[t] = v;
    __syncthreads();
    #pragma unroll
    for (int d = 1; d < 128; d <<= 1) {
        int x = s[t];
        if (t >= d) x += s[t - d];
        __syncthreads();
        s[t] = x;
        __syncthreads();
    }
    if (t < nb) g_boff[t] = s[t] - v;                // exclusive
}

// finalize offsets + cursors, write sentinel, and per-graph starts (batch sorted)
__global__ void k_scan3(const int* __restrict__ batch, int n, int E) {
    int i = blockIdx.x * blockDim.x + threadIdx.x;
    if (i >= n) return;
    int o = g_off[i] + g_boff[i >> 10];
    g_off[i] = o;
    g_cur[i] = o;
    if (i == 0) g_off[n] = E;
    int b = batch[i];
    int p = (i == 0) ? -1 : batch[i - 1];
    for (int g = p + 1; g <= b; ++g) g_gs[g] = i;
    if (i == n - 1)
        for (int g = b + 1; g <= G_NUM; ++g) g_gs[g] = n;
}

// scatter edges into CSR slots; partial norm (dis[row]*ew) — dis[col] folded
// into the gather as a per-node constant.
__global__ void k_place(const int* __restrict__ row,
                        const int* __restrict__ col,
                        const float* __restrict__ ew, int E) {
    int e = blockIdx.x * blockDim.x + threadIdx.x;
    if (e >= E) return;
    int r = row[e];
    int c = col[e];
    float nm = g_dis[r] * ew[e];
    int pos = atomicAdd(&g_cur[c], 1);
    g_edge[pos] = make_float2(__int_as_float(r), nm);
}

// GEMM: g_h[n][HID] = X[n][K] @ W[K][HID]; SRC_ACC reads relu(g_acc).
// 256 thr/CTA, 32 rows/CTA, thread computes 2 rows x 4 cols via fp32x2 FMA.
template<int K, bool SRC_ACC>
__global__ void k_gemm(const float* __restrict__ X,
                       const float* __restrict__ W, int n) {
    __shared__ float sw[K * HID];
    __shared__ float sx[32 * K];
    const int t = threadIdx.x;
    const int row0 = blockIdx.x * 32;

    #pragma unroll
    for (int i = t; i < K * HID / 4; i += 256)
        ((float4*)sw)[i] = ((const float4*)W)[i];

    #pragma unroll
    for (int i = t; i < 32 * K / 4; i += 256) {
        int rr = i / (K / 4);
        int cc = i % (K / 4);
        int grow = row0 + rr;
        if (grow >= n) grow = n - 1;
        float4 v = SRC_ACC
            ? ((const float4*)(g_acc + (size_t)grow * K))[cc]
            : ((const float4*)(X     + (size_t)grow * K))[cc];
        if (SRC_ACC) {
            v.x = fmaxf(v.x, 0.0f); v.y = fmaxf(v.y, 0.0f);
            v.z = fmaxf(v.z, 0.0f); v.w = fmaxf(v.w, 0.0f);
        }
        ((float4*)sx)[i] = v;
    }
    __syncthreads();

    const int r  = t >> 4;        // 0..15 (rows r and r+16)
    const int hq = t & 15;        // float4 column group
    u64 a00 = 0, a01 = 0, a10 = 0, a11 = 0;
    const float* xr0 = sx + r * K;
    const float* xr1 = sx + (r + 16) * K;
    #pragma unroll 8
    for (int k = 0; k < K; k++) {
        float4 w = ((const float4*)(sw + k * HID))[hq];
        u64 wlo = pack2(w.x, w.y);
        u64 whi = pack2(w.z, w.w);
        float x0 = xr0[k], x1 = xr1[k];
        u64 x0p = pack2(x0, x0);
        u64 x1p = pack2(x1, x1);
        a00 = ffma2(x0p, wlo, a00); a01 = ffma2(x0p, whi, a01);
        a10 = ffma2(x1p, wlo, a10); a11 = ffma2(x1p, whi, a11);
    }
    int gr0 = row0 + r, gr1 = row0 + r + 16;
    if (gr0 < n) {
        float2 lo = unpack2(a00), hi = unpack2(a01);
        ((float4*)(g_h + (size_t)gr0 * HID))[hq] = make_float4(lo.x, lo.y, hi.x, hi.y);
    }
    if (gr1 < n) {
        float2 lo = unpack2(a10), hi = unpack2(a11);
        ((float4*)(g_h + (size_t)gr1 * HID))[hq] = make_float4(lo.x, lo.y, hi.x, hi.y);
    }
}

// per-node CSR gather: 16 lanes/node, lane owns one float4 column chunk.
// out = bias + dis^2*h[self] + dis[node] * sum_e (dis[row_e]*ew_e) * h[row_e]
__global__ void k_gather(const float* __restrict__ b, int n) {
    int tid = blockIdx.x * blockDim.x + threadIdx.x;
    int node = tid >> 4;
    if (node >= n) return;
    const int q = tid & 15;

    int e     = g_off[node];
    const int e_end = g_off[node + 1];

    u64 e0 = 0, e1 = 0;   // packed edge accumulators (4 floats)

    for (; e + 3 < e_end; e += 4) {
        float2 rA = g_edge[e];
        float2 rB = g_edge[e + 1];
        float2 rC = g_edge[e + 2];
        float2 rD = g_edge[e + 3];
        float4 vA = ((const float4*)(g_h + (size_t)__float_as_int(rA.x) * HID))[q];
        float4 vB = ((const float4*)(g_h + (size_t)__float_as_int(rB.x) * HID))[q];
        float4 vC = ((const float4*)(g_h + (size_t)__float_as_int(rC.x) * HID))[q];
        float4 vD = ((const float4*)(g_h + (size_t)__float_as_int(rD.x) * HID))[q];
        u64 nA = pack2(rA.y, rA.y), nB = pack2(rB.y, rB.y);
        u64 nC = pack2(rC.y, rC.y), nD = pack2(rD.y, rD.y);
        e0 = ffma2(nA, pack2(vA.x, vA.y), e0); e1 = ffma2(nA, pack2(vA.z, vA.w), e1);
        e0 = ffma2(nB, pack2(vB.x, vB.y), e0); e1 = ffma2(nB, pack2(vB.z, vB.w), e1);
        e0 = ffma2(nC, pack2(vC.x, vC.y), e0); e1 = ffma2(nC, pack2(vC.z, vC.w), e1);
        e0 = ffma2(nD, pack2(vD.x, vD.y), e0); e1 = ffma2(nD, pack2(vD.z, vD.w), e1);
    }
    for (; e < e_end; e++) {
        float2 r0 = g_edge[e];
        float4 v0 = ((const float4*)(g_h + (size_t)__float_as_int(r0.x) * HID))[q];
        u64 n0 = pack2(r0.y, r0.y);
        e0 = ffma2(n0, pack2(v0.x, v0.y), e0);
        e1 = ffma2(n0, pack2(v0.z, v0.w), e1);
    }

    const float d  = g_dis[node];
    const float dd = d * d;
    float4 bq = ((const float4*)b)[q];
    float4 h0 = ((const float4*)(g_h + (size_t)node * HID))[q];
    float2 lo = unpack2(e0), hi = unpack2(e1);
    float4 out;
    out.x = bq.x + dd * h0.x + d * lo.x;
    out.y = bq.y + dd * h0.y + d * lo.y;
    out.z = bq.z + dd * h0.z + d * hi.x;
    out.w = bq.w + dd * h0.w + d * hi.y;
    ((float4*)(g_acc + (size_t)node * HID))[q] = out;
}

// one CTA per graph: sum relu(g_acc) over the graph's contiguous node range
__global__ void k_pool(int n) {
    const int g = blockIdx.x;
    const int t = threadIdx.x;
    const int q = t & 15;
    const int sub = t >> 4;
    const int s = g_gs[g], e = g_gs[g + 1];

    float4 acc = make_float4(0.f, 0.f, 0.f, 0.f);
    for (int i = s + sub; i < e; i += 16) {
        float4 v = ((const float4*)(g_acc + (size_t)i * HID))[q];
        acc.x += fmaxf(v.x, 0.f); acc.y += fmaxf(v.y, 0.f);
        acc.z += fmaxf(v.z, 0.f); acc.w += fmaxf(v.w, 0.f);
    }
    __shared__ float4 sm[256];
    sm[t] = acc;
    __syncthreads();
    if (sub == 0) {
        float4 a = acc;
        #pragma unroll
        for (int k = 1; k < 16; k++) {
            float4 bb = sm[k * 16 + q];
            a.x += bb.x; a.y += bb.y; a.z += bb.z; a.w += bb.w;
        }
        ((float4*)(g_sums + g * HID))[q] = a;
        if (q == 0) g_gcnt[g] = e - s;
    }
}

__global__ void k_final(const float* __restrict__ Wc,
                        const float* __restrict__ bc,
                        float* __restrict__ out) {
    int g = blockIdx.x * blockDim.x + threadIdx.x;
    if (g >= G_NUM) return;
    const float c = fmaxf((float)g_gcnt[g], 1.0f);
    float acc = 0.0f;
    #pragma unroll
    for (int h = 0; h < HID; h++)
        acc += g_sums[g * HID + h] * Wc[h];
    out[g] = acc / c + bc[0];
}

// ---------------- launcher ----------------
extern "C" void kernel_launch(void* const* d_in, const int* in_sizes, int n_in,
                              void* d_out, int out_size) {
    const float* x     = (const float*)d_in[0];
    const int*   ei    = (const int*)  d_in[1];   // int32 (JAX x64 disabled)
    const float* ew    = (const float*)d_in[2];
    const int*   batch = (const int*)  d_in[3];   // int32
    const float* W1    = (const float*)d_in[4];
    const float* b1    = (const float*)d_in[5];
    const float* W2    = (const float*)d_in[6];
    const float* b2    = (const float*)d_in[7];
    const float* Wc    = (const float*)d_in[8];
    const float* bc    = (const float*)d_in[9];
    float* out = (float*)d_out;

    const int n = in_sizes[0] / IN_DIM;   // 100000
    const int E = in_sizes[2];            // 3200000
    const int* row = ei;
    const int* col = ei + E;
    const int T = 256;
    const int nb = (n + SCAN_B - 1) / SCAN_B;

    k_reset<<<(n + T - 1) / T, T>>>(n);
    k_deg  <<<(E + T - 1) / T, T>>>(col, ew, E);
    k_scan1<<<nb, SCAN_B>>>(n);
    k_gemm<IN_DIM, false><<<(n + 31) / 32, T>>>(x, W1, n);   // independent; also lands in ncu slot
    k_scan2<<<1, 128>>>(nb);
    k_scan3<<<(n + T - 1) / T, T>>>(batch, n, E);
    k_place<<<(E + T - 1) / T, T>>>(row, col, ew, E);

    k_gather<<<(n * 16 + T - 1) / T, T>>>(b1, n);            // layer 1

    k_gemm<HID, true><<<(n + 31) / 32, T>>>(nullptr, W2, n); // layer 2
    k_gather<<<(n * 16 + T - 1) / T, T>>>(b2, n);

    k_pool <<<G_NUM, 256>>>(n);
    k_final<<<1, T>>>(Wc, bc, out);
}